// round 3
// baseline (speedup 1.0000x reference)
#include <cuda_runtime.h>

// Problem constants: B=32, T=4, L=256, D=768
#define DDIM 768
#define MTOT 32768
#define NPOS 8192

__device__ float g_Y[(size_t)MTOT * DDIM];   // GEMM out / LN in, tble order
__device__ float g_S[(size_t)MTOT * DDIM];   // layer-1 spikes, tble order

// ---------------------------------------------------------------------------
// SGEMM bit-matching Eigen gebp (XLA:CPU reference):
//   per output element: ((p0 + p1) + p2), kc-panels of d = [0,320), [320,640),
//   [640,768); within each panel a strict ascending single-accumulator FMA
//   chain; panels combined with one rounded add each.
// ---------------------------------------------------------------------------
__global__ __launch_bounds__(256, 1) void sgemm_kernel(
    const float* __restrict__ Ain, const float* __restrict__ W,
    const float* __restrict__ bias, int permute)
{
    __shared__ float As[2][8][128];
    __shared__ float Bs[2][8][128];

    const float* A = permute ? Ain : g_S;
    float* C = g_Y;

    int tid = threadIdx.x;
    int bx = blockIdx.x;   // N tile: 0..5
    int by = blockIdx.y;   // M tile: 0..255

    int lrow = tid >> 1;
    int lkk  = (tid & 1) << 2;

    int arow = (by << 7) + lrow;
    int srow = arow;
    if (permute) {
        int t = arow >> 13;
        int b = (arow >> 8) & 31;
        int l = arow & 255;
        srow = (b << 10) + (t << 8) + l;   // b*T*L + t*L + l
    }
    const float* aptr = A + (size_t)srow * DDIM + lkk;
    const float* bptr = W + (size_t)((bx << 7) + lrow) * DDIM + lkk;

    float acc[8][8];   // current panel chain
    float tot[8][8];   // running cross-panel total
    #pragma unroll
    for (int i = 0; i < 8; i++)
        #pragma unroll
        for (int j = 0; j < 8; j++) { acc[i][j] = 0.f; tot[i][j] = 0.f; }

    {
        float4 a4 = *(const float4*)aptr;
        float4 b4 = *(const float4*)bptr;
        As[0][lkk + 0][lrow] = a4.x; As[0][lkk + 1][lrow] = a4.y;
        As[0][lkk + 2][lrow] = a4.z; As[0][lkk + 3][lrow] = a4.w;
        Bs[0][lkk + 0][lrow] = b4.x; Bs[0][lkk + 1][lrow] = b4.y;
        Bs[0][lkk + 2][lrow] = b4.z; Bs[0][lkk + 3][lrow] = b4.w;
    }
    __syncthreads();

    int tx = tid & 15;
    int ty = tid >> 4;

    const int KT = DDIM / 8;  // 96; panel boundaries after kt=39 (d=320) and kt=79 (d=640)
    for (int kt = 0; kt < KT; kt++) {
        int cur = kt & 1;
        float4 na, nb;
        if (kt < KT - 1) {
            na = *(const float4*)(aptr + (kt + 1) * 8);
            nb = *(const float4*)(bptr + (kt + 1) * 8);
        }
        #pragma unroll
        for (int k = 0; k < 8; k++) {
            float a[8], b[8];
            *(float4*)(a)     = *(const float4*)&As[cur][k][ty * 8];
            *(float4*)(a + 4) = *(const float4*)&As[cur][k][ty * 8 + 4];
            *(float4*)(b)     = *(const float4*)&Bs[cur][k][tx * 8];
            *(float4*)(b + 4) = *(const float4*)&Bs[cur][k][tx * 8 + 4];
            #pragma unroll
            for (int i = 0; i < 8; i++)
                #pragma unroll
                for (int j = 0; j < 8; j++)
                    acc[i][j] = __fmaf_rn(a[i], b[j], acc[i][j]);
        }
        // Eigen kc=320 panel boundary: fold panel chain into running total
        if (kt == 39 || kt == 79) {
            #pragma unroll
            for (int i = 0; i < 8; i++)
                #pragma unroll
                for (int j = 0; j < 8; j++) {
                    tot[i][j] = __fadd_rn(tot[i][j], acc[i][j]);
                    acc[i][j] = 0.f;
                }
        }
        if (kt < KT - 1) {
            int nxt = cur ^ 1;
            As[nxt][lkk + 0][lrow] = na.x; As[nxt][lkk + 1][lrow] = na.y;
            As[nxt][lkk + 2][lrow] = na.z; As[nxt][lkk + 3][lrow] = na.w;
            Bs[nxt][lkk + 0][lrow] = nb.x; Bs[nxt][lkk + 1][lrow] = nb.y;
            Bs[nxt][lkk + 2][lrow] = nb.z; Bs[nxt][lkk + 3][lrow] = nb.w;
            __syncthreads();
        }
    }

    int e0 = (bx << 7) + tx * 8;
    #pragma unroll
    for (int i = 0; i < 8; i++) {
        int r = (by << 7) + ty * 8 + i;
        float* cp = C + (size_t)r * DDIM + e0;
        #pragma unroll
        for (int j = 0; j < 8; j++) {
            float v = __fadd_rn(tot[i][j], acc[i][j]);   // fold last panel
            cp[j] = __fadd_rn(v, bias[e0 + j]);
        }
    }
}

// ---------------------------------------------------------------------------
// Fused LayerNorm + LIF, XLA:CPU-matching arithmetic (strict sequential
// in-order sums, correctly-rounded div/sqrt, no contraction).
// One warp per (b,l) position.
// ---------------------------------------------------------------------------
__global__ __launch_bounds__(256) void ln_lif_kernel(
    const float* __restrict__ gamma, const float* __restrict__ beta,
    float* __restrict__ outp, int final_out)
{
    __shared__ float srow[8][DDIM];
    int warp = threadIdx.x >> 5, lane = threadIdx.x & 31;
    int p = (blockIdx.x << 3) + warp;
    int b = p >> 8, l = p & 255;

    float g[24], bb[24], v[24], y[24];
    #pragma unroll
    for (int j = 0; j < 24; j++) {
        g[j]  = gamma[lane + 32 * j];
        bb[j] = beta[lane + 32 * j];
        v[j]  = 0.f;
    }

    for (int t = 0; t < 4; t++) {
        const float* row = g_Y + (size_t)(t * NPOS + p) * DDIM;
        #pragma unroll
        for (int j = 0; j < 24; j++) {
            y[j] = row[lane + 32 * j];
            srow[warp][lane + 32 * j] = y[j];
        }
        __syncwarp();

        float mu = 0.f, r = 0.f;
        if (lane == 0) {
            float acc = 0.f;
            #pragma unroll 8
            for (int d = 0; d < DDIM; d++)
                acc = __fadd_rn(acc, srow[warp][d]);
            mu = __fdiv_rn(acc, 768.0f);
            float ssq = 0.f;
            #pragma unroll 8
            for (int d = 0; d < DDIM; d++) {
                float df = __fadd_rn(srow[warp][d], -mu);
                ssq = __fadd_rn(ssq, __fmul_rn(df, df));
            }
            float var = __fdiv_rn(ssq, 768.0f);
            r = __fdiv_rn(1.0f, __fsqrt_rn(__fadd_rn(var, 1e-5f)));
        }
        mu = __shfl_sync(0xffffffffu, mu, 0);
        r  = __shfl_sync(0xffffffffu, r, 0);

        float* dst = final_out
            ? outp + (size_t)((((b << 2) + t) << 8) + l) * DDIM   // [B,T,L,D]
            : g_S + (size_t)(t * NPOS + p) * DDIM;                 // tble

        #pragma unroll
        for (int j = 0; j < 24; j++) {
            float h = __fadd_rn(
                __fmul_rn(__fmul_rn(__fadd_rn(y[j], -mu), r), g[j]), bb[j]);
            float dlt = __fmul_rn(__fadd_rn(h, -v[j]), 0.5f);
            v[j] = __fadd_rn(v[j], dlt);
            float s = (v[j] >= 1.0f) ? 1.0f : 0.0f;
            dst[lane + 32 * j] = s;
            v[j] = __fmul_rn(v[j], __fadd_rn(1.0f, -s));
        }
        __syncwarp();
    }
}

// ---------------------------------------------------------------------------
extern "C" void kernel_launch(void* const* d_in, const int* in_sizes, int n_in,
                              void* d_out, int out_size)
{
    const float* x   = (const float*)d_in[0];
    const float* W1  = (const float*)d_in[1];
    const float* b1  = (const float*)d_in[2];
    const float* g1  = (const float*)d_in[3];
    const float* be1 = (const float*)d_in[4];
    const float* W2  = (const float*)d_in[5];
    const float* b2  = (const float*)d_in[6];
    const float* g2  = (const float*)d_in[7];
    const float* be2 = (const float*)d_in[8];
    float* out = (float*)d_out;

    dim3 gg(DDIM / 128, MTOT / 128);   // (6, 256)

    sgemm_kernel<<<gg, 256>>>(x, W1, b1, 1);
    ln_lif_kernel<<<NPOS / 8, 256>>>(g1, be1, nullptr, 0);

    sgemm_kernel<<<gg, 256>>>(nullptr, W2, b2, 0);
    ln_lif_kernel<<<NPOS / 8, 256>>>(g2, be2, out, 1);
}

// round 4
// speedup vs baseline: 1.0724x; 1.0724x over previous
#include <cuda_runtime.h>
#include <stdint.h>

// Problem constants: B=32, T=4, L=256, D=768
#define DDIM 768
#define MTOT 32768
#define NPOS 8192

__device__ float    g_Y[(size_t)MTOT * DDIM];      // GEMM out / LN in, tble order
__device__ float    g_Wt[DDIM * DDIM];             // W2 transposed: g_Wt[d][e]
__device__ uint16_t g_idx[(size_t)MTOT * DDIM];    // per-row ascending nonzero d list
__device__ int4     g_cnt[MTOT];                   // x=c1(<320), y=c2(<640), z=nnz

// ---------------------------------------------------------------------------
// Dense SGEMM for layer 1, bit-matching Eigen gebp (XLA:CPU):
// per element ((p0+p1)+p2)+bias, panels d=[0,320),[320,640),[640,768),
// ascending single-accumulator FMA chain inside each panel.
// A rows come from x[B,T,L,D] with btld->tble permutation.
// ---------------------------------------------------------------------------
__global__ __launch_bounds__(256, 1) void sgemm_kernel(
    const float* __restrict__ A, const float* __restrict__ W,
    const float* __restrict__ bias)
{
    __shared__ float As[2][8][128];
    __shared__ float Bs[2][8][128];

    int tid = threadIdx.x;
    int bx = blockIdx.x;   // N tile 0..5
    int by = blockIdx.y;   // M tile 0..255

    int lrow = tid >> 1;
    int lkk  = (tid & 1) << 2;

    int arow = (by << 7) + lrow;          // tble row
    int t = arow >> 13;
    int b = (arow >> 8) & 31;
    int l = arow & 255;
    int srow = (b << 10) + (t << 8) + l;  // b*T*L + t*L + l

    const float* aptr = A + (size_t)srow * DDIM + lkk;
    const float* bptr = W + (size_t)((bx << 7) + lrow) * DDIM + lkk;

    float acc[8][8], tot[8][8];
    #pragma unroll
    for (int i = 0; i < 8; i++)
        #pragma unroll
        for (int j = 0; j < 8; j++) { acc[i][j] = 0.f; tot[i][j] = 0.f; }

    {
        float4 a4 = *(const float4*)aptr;
        float4 b4 = *(const float4*)bptr;
        As[0][lkk + 0][lrow] = a4.x; As[0][lkk + 1][lrow] = a4.y;
        As[0][lkk + 2][lrow] = a4.z; As[0][lkk + 3][lrow] = a4.w;
        Bs[0][lkk + 0][lrow] = b4.x; Bs[0][lkk + 1][lrow] = b4.y;
        Bs[0][lkk + 2][lrow] = b4.z; Bs[0][lkk + 3][lrow] = b4.w;
    }
    __syncthreads();

    int tx = tid & 15;
    int ty = tid >> 4;

    const int KT = DDIM / 8;  // 96; fold after kt=39 (d=320) and kt=79 (d=640)
    for (int kt = 0; kt < KT; kt++) {
        int cur = kt & 1;
        float4 na, nb;
        if (kt < KT - 1) {
            na = *(const float4*)(aptr + (kt + 1) * 8);
            nb = *(const float4*)(bptr + (kt + 1) * 8);
        }
        #pragma unroll
        for (int k = 0; k < 8; k++) {
            float a[8], bf[8];
            *(float4*)(a)      = *(const float4*)&As[cur][k][ty * 8];
            *(float4*)(a + 4)  = *(const float4*)&As[cur][k][ty * 8 + 4];
            *(float4*)(bf)     = *(const float4*)&Bs[cur][k][tx * 8];
            *(float4*)(bf + 4) = *(const float4*)&Bs[cur][k][tx * 8 + 4];
            #pragma unroll
            for (int i = 0; i < 8; i++)
                #pragma unroll
                for (int j = 0; j < 8; j++)
                    acc[i][j] = __fmaf_rn(a[i], bf[j], acc[i][j]);
        }
        if (kt == 39 || kt == 79) {
            #pragma unroll
            for (int i = 0; i < 8; i++)
                #pragma unroll
                for (int j = 0; j < 8; j++) {
                    tot[i][j] = __fadd_rn(tot[i][j], acc[i][j]);
                    acc[i][j] = 0.f;
                }
        }
        if (kt < KT - 1) {
            int nxt = cur ^ 1;
            As[nxt][lkk + 0][lrow] = na.x; As[nxt][lkk + 1][lrow] = na.y;
            As[nxt][lkk + 2][lrow] = na.z; As[nxt][lkk + 3][lrow] = na.w;
            Bs[nxt][lkk + 0][lrow] = nb.x; Bs[nxt][lkk + 1][lrow] = nb.y;
            Bs[nxt][lkk + 2][lrow] = nb.z; Bs[nxt][lkk + 3][lrow] = nb.w;
            __syncthreads();
        }
    }

    int e0 = (bx << 7) + tx * 8;
    #pragma unroll
    for (int i = 0; i < 8; i++) {
        int r = (by << 7) + ty * 8 + i;
        float* cp = g_Y + (size_t)r * DDIM + e0;
        #pragma unroll
        for (int j = 0; j < 8; j++) {
            float v = __fadd_rn(tot[i][j], acc[i][j]);
            cp[j] = __fadd_rn(v, bias[e0 + j]);
        }
    }
}

// ---------------------------------------------------------------------------
// W2 transpose: g_Wt[d][e] = W2[e][d].  grid (24,24), block (32,8).
// ---------------------------------------------------------------------------
__global__ void transpose_kernel(const float* __restrict__ W)
{
    __shared__ float tile[32][33];
    int bx = blockIdx.x << 5, by = blockIdx.y << 5;
    int x = bx + threadIdx.x;
    #pragma unroll
    for (int i = 0; i < 32; i += 8)
        tile[threadIdx.y + i][threadIdx.x] =
            W[(size_t)(by + threadIdx.y + i) * DDIM + x];
    __syncthreads();
    int x2 = by + threadIdx.x;
    #pragma unroll
    for (int i = 0; i < 32; i += 8)
        g_Wt[(size_t)(bx + threadIdx.y + i) * DDIM + x2] =
            tile[threadIdx.x][threadIdx.y + i];
}

// ---------------------------------------------------------------------------
// Fused LayerNorm + LIF (bit-matching XLA:CPU): strict sequential in-order
// sums on lane 0, correctly-rounded div/sqrt, uncontracted elementwise ops.
// final_out==0: emit ascending nonzero-d index lists + panel counts (for the
//               sparse layer-2 GEMM) instead of dense spikes.
// final_out==1: write dense spikes transposed to out[B,T,L,D].
// One warp per (b,l) position; LIF state v carried in registers across t.
// ---------------------------------------------------------------------------
__global__ __launch_bounds__(256, 4) void ln_lif_kernel(
    const float* __restrict__ gamma, const float* __restrict__ beta,
    float* __restrict__ outp, int final_out)
{
    __shared__ float srow[8][DDIM];
    int warp = threadIdx.x >> 5, lane = threadIdx.x & 31;
    int p = (blockIdx.x << 3) + warp;
    int b = p >> 8, l = p & 255;

    float v[24];
    #pragma unroll
    for (int j = 0; j < 24; j++) v[j] = 0.f;

    for (int t = 0; t < 4; t++) {
        int r = t * NPOS + p;
        const float* row = g_Y + (size_t)r * DDIM;
        #pragma unroll
        for (int j = 0; j < 24; j++)
            srow[warp][lane + (j << 5)] = row[lane + (j << 5)];
        __syncwarp();

        float mu = 0.f, rstd = 0.f;
        if (lane == 0) {
            float acc = 0.f;
            #pragma unroll 8
            for (int d = 0; d < DDIM; d++)
                acc = __fadd_rn(acc, srow[warp][d]);
            mu = __fdiv_rn(acc, 768.0f);
            float ssq = 0.f;
            #pragma unroll 8
            for (int d = 0; d < DDIM; d++) {
                float df = __fadd_rn(srow[warp][d], -mu);
                ssq = __fadd_rn(ssq, __fmul_rn(df, df));
            }
            float var = __fdiv_rn(ssq, 768.0f);
            rstd = __fdiv_rn(1.0f, __fsqrt_rn(__fadd_rn(var, 1e-5f)));
        }
        mu   = __shfl_sync(0xffffffffu, mu, 0);
        rstd = __shfl_sync(0xffffffffu, rstd, 0);

        if (final_out) {
            float* dst = outp + (size_t)((((b << 2) + t) << 8) + l) * DDIM;
            #pragma unroll
            for (int j = 0; j < 24; j++) {
                int d = lane + (j << 5);
                float x = srow[warp][d];
                float h = __fadd_rn(
                    __fmul_rn(__fmul_rn(__fadd_rn(x, -mu), rstd), gamma[d]),
                    beta[d]);
                float dlt = __fmul_rn(__fadd_rn(h, -v[j]), 0.5f);
                v[j] = __fadd_rn(v[j], dlt);
                float s = (v[j] >= 1.0f) ? 1.0f : 0.0f;
                dst[d] = s;
                v[j] = __fmul_rn(v[j], __fadd_rn(1.0f, -s));
            }
        } else {
            uint16_t* ip = g_idx + (size_t)r * DDIM;
            int base = 0, c1 = 0, c2 = 0;
            #pragma unroll
            for (int j = 0; j < 24; j++) {      // chunk j covers d=[32j,32j+32)
                int d = lane + (j << 5);
                float x = srow[warp][d];
                float h = __fadd_rn(
                    __fmul_rn(__fmul_rn(__fadd_rn(x, -mu), rstd), gamma[d]),
                    beta[d]);
                float dlt = __fmul_rn(__fadd_rn(h, -v[j]), 0.5f);
                v[j] = __fadd_rn(v[j], dlt);
                float s = (v[j] >= 1.0f) ? 1.0f : 0.0f;
                unsigned msk = __ballot_sync(0xffffffffu, s == 1.0f);
                if (s == 1.0f) {
                    int pos = base + __popc(msk & ((1u << lane) - 1u));
                    ip[pos] = (uint16_t)d;
                }
                base += __popc(msk);
                v[j] = __fmul_rn(v[j], __fadd_rn(1.0f, -s));
                if (j == 9)  c1 = base;   // d<320 boundary
                if (j == 19) c2 = base;   // d<640 boundary
            }
            if (lane == 0) g_cnt[r] = make_int4(c1, c2, base, 0);
        }
        __syncwarp();
    }
}

// ---------------------------------------------------------------------------
// Sparse layer-2 GEMM: spikes are exactly 0/1, so the Eigen chain reduces to
// summing W2[e,d] over the row's nonzero d's in ascending order — bit-exact
// (fma(0,w,acc)==acc, fma(1,w,acc)==fadd(acc,w) in RN), keeping the panel
// folds ((p0+p1)+p2)+bias.  One warp per output row; W2^T gathers coalesced.
// ---------------------------------------------------------------------------
__global__ __launch_bounds__(256) void spmm_kernel(const float* __restrict__ bias)
{
    int warp = threadIdx.x >> 5, lane = threadIdx.x & 31;
    int r = (blockIdx.x << 3) + warp;

    int4 cnt = g_cnt[r];
    int bounds[4] = {0, cnt.x, cnt.y, cnt.z};
    const uint16_t* idx = g_idx + (size_t)r * DDIM;

    float4 tot[6];
    #pragma unroll
    for (int j = 0; j < 6; j++) tot[j] = make_float4(0.f, 0.f, 0.f, 0.f);

    #pragma unroll
    for (int pnl = 0; pnl < 3; pnl++) {
        float4 pan[6];
        #pragma unroll
        for (int j = 0; j < 6; j++) pan[j] = make_float4(0.f, 0.f, 0.f, 0.f);
        int lo = bounds[pnl], hi = bounds[pnl + 1];
        for (int kb = lo; kb < hi; kb += 32) {
            int n = min(32, hi - kb);
            int myd = (kb + lane < hi) ? (int)idx[kb + lane] : 0;
            for (int kk = 0; kk < n; kk++) {
                int d = __shfl_sync(0xffffffffu, myd, kk);
                const float4* w = (const float4*)(g_Wt + d * DDIM);
                #pragma unroll
                for (int j = 0; j < 6; j++) {
                    float4 w4 = w[lane + (j << 5)];
                    pan[j].x = __fadd_rn(pan[j].x, w4.x);
                    pan[j].y = __fadd_rn(pan[j].y, w4.y);
                    pan[j].z = __fadd_rn(pan[j].z, w4.z);
                    pan[j].w = __fadd_rn(pan[j].w, w4.w);
                }
            }
        }
        #pragma unroll
        for (int j = 0; j < 6; j++) {
            tot[j].x = __fadd_rn(tot[j].x, pan[j].x);
            tot[j].y = __fadd_rn(tot[j].y, pan[j].y);
            tot[j].z = __fadd_rn(tot[j].z, pan[j].z);
            tot[j].w = __fadd_rn(tot[j].w, pan[j].w);
        }
    }

    float4* orow = (float4*)(g_Y + (size_t)r * DDIM);
    const float4* b4 = (const float4*)bias;
    #pragma unroll
    for (int j = 0; j < 6; j++) {
        int e4 = lane + (j << 5);
        float4 bb = b4[e4];
        float4 o;
        o.x = __fadd_rn(tot[j].x, bb.x);
        o.y = __fadd_rn(tot[j].y, bb.y);
        o.z = __fadd_rn(tot[j].z, bb.z);
        o.w = __fadd_rn(tot[j].w, bb.w);
        orow[e4] = o;
    }
}

// ---------------------------------------------------------------------------
extern "C" void kernel_launch(void* const* d_in, const int* in_sizes, int n_in,
                              void* d_out, int out_size)
{
    const float* x   = (const float*)d_in[0];
    const float* W1  = (const float*)d_in[1];
    const float* b1  = (const float*)d_in[2];
    const float* g1  = (const float*)d_in[3];
    const float* be1 = (const float*)d_in[4];
    const float* W2  = (const float*)d_in[5];
    const float* b2  = (const float*)d_in[6];
    const float* g2  = (const float*)d_in[7];
    const float* be2 = (const float*)d_in[8];
    float* out = (float*)d_out;

    dim3 gg(DDIM / 128, MTOT / 128);   // (6, 256)

    transpose_kernel<<<dim3(24, 24), dim3(32, 8)>>>(W2);
    sgemm_kernel<<<gg, 256>>>(x, W1, b1);
    ln_lif_kernel<<<NPOS / 8, 256>>>(g1, be1, nullptr, 0);   // -> idx lists
    spmm_kernel<<<MTOT / 8, 256>>>(b2);                      // sparse GEMM2
    ln_lif_kernel<<<NPOS / 8, 256>>>(g2, be2, out, 1);       // -> final spikes
}

// round 5
// speedup vs baseline: 1.7131x; 1.5974x over previous
#include <cuda_runtime.h>
#include <stdint.h>

// Problem constants: B=32, T=4, L=256, D=768
#define DDIM 768
#define MTOT 32768
#define NPOS 8192

typedef unsigned long long ull;

__device__ float    g_Y[(size_t)MTOT * DDIM];      // GEMM out / LN in, tble order
__device__ float    g_Wt[DDIM * DDIM];             // W2 transposed: g_Wt[d][e]
__device__ uint16_t g_idx[(size_t)MTOT * DDIM];    // per-row ascending nonzero d list
__device__ int4     g_cnt[MTOT];                   // x=c1(<320), y=c2(<640), z=nnz

// Packed f32x2 ops (each half is an independent IEEE-RN op -> bit-exact chains)
#define FMA2(d, a, b, c) \
    asm("fma.rn.f32x2 %0, %1, %2, %3;" : "=l"(d) : "l"(a), "l"(b), "l"(c))
#define ADD2(d, a, b) \
    asm("add.rn.f32x2 %0, %1, %2;" : "=l"(d) : "l"(a), "l"(b))
#define PACK2(d, lo, hi) \
    asm("mov.b64 %0, {%1, %2};" : "=l"(d) : "r"(lo), "r"(hi))
#define UNPACK2(lo, hi, s) \
    asm("mov.b64 {%0, %1}, %2;" : "=r"(lo), "=r"(hi) : "l"(s))

// ---------------------------------------------------------------------------
// Dense SGEMM for layer 1, bit-matching Eigen gebp (XLA:CPU):
// per element ((p0+p1)+p2)+bias, panels d=[0,320),[320,640),[640,768),
// ascending single-accumulator FMA chain inside each panel.
// Inner product uses fma.rn.f32x2 (2 accumulator chains per instr; each lane
// of the packed op is its own IEEE-RN chain -> bit-identical to scalar).
// ---------------------------------------------------------------------------
__global__ __launch_bounds__(256, 1) void sgemm_kernel(
    const float* __restrict__ A, const float* __restrict__ W,
    const float* __restrict__ bias)
{
    __shared__ float As[2][8][128];
    __shared__ float Bs[2][8][128];

    int tid = threadIdx.x;
    int bx = blockIdx.x;   // N tile 0..5
    int by = blockIdx.y;   // M tile 0..255

    int lrow = tid >> 1;
    int lkk  = (tid & 1) << 2;

    int arow = (by << 7) + lrow;          // tble row
    int t = arow >> 13;
    int b = (arow >> 8) & 31;
    int l = arow & 255;
    int srow = (b << 10) + (t << 8) + l;  // b*T*L + t*L + l

    const float* aptr = A + (size_t)srow * DDIM + lkk;
    const float* bptr = W + (size_t)((bx << 7) + lrow) * DDIM + lkk;

    ull acc2[8][4], tot2[8][4];
    #pragma unroll
    for (int i = 0; i < 8; i++)
        #pragma unroll
        for (int j = 0; j < 4; j++) { acc2[i][j] = 0ull; tot2[i][j] = 0ull; }

    {
        float4 a4 = *(const float4*)aptr;
        float4 b4 = *(const float4*)bptr;
        As[0][lkk + 0][lrow] = a4.x; As[0][lkk + 1][lrow] = a4.y;
        As[0][lkk + 2][lrow] = a4.z; As[0][lkk + 3][lrow] = a4.w;
        Bs[0][lkk + 0][lrow] = b4.x; Bs[0][lkk + 1][lrow] = b4.y;
        Bs[0][lkk + 2][lrow] = b4.z; Bs[0][lkk + 3][lrow] = b4.w;
    }
    __syncthreads();

    int tx = tid & 15;
    int ty = tid >> 4;

    const int KT = DDIM / 8;  // 96; fold after kt=39 (d=320) and kt=79 (d=640)
    for (int kt = 0; kt < KT; kt++) {
        int cur = kt & 1;
        float4 na, nb;
        if (kt < KT - 1) {
            na = *(const float4*)(aptr + (kt + 1) * 8);
            nb = *(const float4*)(bptr + (kt + 1) * 8);
        }
        #pragma unroll
        for (int k = 0; k < 8; k++) {
            float a[8];
            *(float4*)(a)     = *(const float4*)&As[cur][k][ty * 8];
            *(float4*)(a + 4) = *(const float4*)&As[cur][k][ty * 8 + 4];
            // b pairs: consecutive j are contiguous in smem -> direct 64-bit loads
            ull b2[4];
            const ull* bp = (const ull*)&Bs[cur][k][tx * 8];
            b2[0] = bp[0]; b2[1] = bp[1]; b2[2] = bp[2]; b2[3] = bp[3];
            ull aa[8];
            #pragma unroll
            for (int i = 0; i < 8; i++) {
                unsigned ai = __float_as_uint(a[i]);
                PACK2(aa[i], ai, ai);
            }
            #pragma unroll
            for (int i = 0; i < 8; i++)
                #pragma unroll
                for (int jp = 0; jp < 4; jp++)
                    FMA2(acc2[i][jp], aa[i], b2[jp], acc2[i][jp]);
        }
        if (kt == 39 || kt == 79) {
            #pragma unroll
            for (int i = 0; i < 8; i++)
                #pragma unroll
                for (int jp = 0; jp < 4; jp++) {
                    ADD2(tot2[i][jp], tot2[i][jp], acc2[i][jp]);
                    acc2[i][jp] = 0ull;
                }
        }
        if (kt < KT - 1) {
            int nxt = cur ^ 1;
            As[nxt][lkk + 0][lrow] = na.x; As[nxt][lkk + 1][lrow] = na.y;
            As[nxt][lkk + 2][lrow] = na.z; As[nxt][lkk + 3][lrow] = na.w;
            Bs[nxt][lkk + 0][lrow] = nb.x; Bs[nxt][lkk + 1][lrow] = nb.y;
            Bs[nxt][lkk + 2][lrow] = nb.z; Bs[nxt][lkk + 3][lrow] = nb.w;
            __syncthreads();
        }
    }

    int e0 = (bx << 7) + tx * 8;
    #pragma unroll
    for (int i = 0; i < 8; i++) {
        int r = (by << 7) + ty * 8 + i;
        float* cp = g_Y + (size_t)r * DDIM + e0;
        #pragma unroll
        for (int jp = 0; jp < 4; jp++) {
            unsigned tl, th, al, ah;
            UNPACK2(tl, th, tot2[i][jp]);
            UNPACK2(al, ah, acc2[i][jp]);
            float v0 = __fadd_rn(__uint_as_float(tl), __uint_as_float(al));
            float v1 = __fadd_rn(__uint_as_float(th), __uint_as_float(ah));
            cp[2 * jp]     = __fadd_rn(v0, bias[e0 + 2 * jp]);
            cp[2 * jp + 1] = __fadd_rn(v1, bias[e0 + 2 * jp + 1]);
        }
    }
}

// ---------------------------------------------------------------------------
// W2 transpose: g_Wt[d][e] = W2[e][d].
// ---------------------------------------------------------------------------
__global__ void transpose_kernel(const float* __restrict__ W)
{
    __shared__ float tile[32][33];
    int bx = blockIdx.x << 5, by = blockIdx.y << 5;
    int x = bx + threadIdx.x;
    #pragma unroll
    for (int i = 0; i < 32; i += 8)
        tile[threadIdx.y + i][threadIdx.x] =
            W[(size_t)(by + threadIdx.y + i) * DDIM + x];
    __syncthreads();
    int x2 = by + threadIdx.x;
    #pragma unroll
    for (int i = 0; i < 32; i += 8)
        g_Wt[(size_t)(bx + threadIdx.y + i) * DDIM + x2] =
            tile[threadIdx.x][threadIdx.y + i];
}

// ---------------------------------------------------------------------------
// Fused LayerNorm + LIF (bit-matching XLA:CPU). No launch_bounds min-blocks:
// needs ~128 regs (round-4's (256,4) forced 64 regs -> local spills, 3x slow).
// final_out==0: emit ascending nonzero-d index lists + panel counts.
// final_out==1: write dense spikes transposed to out[B,T,L,D].
// ---------------------------------------------------------------------------
__global__ __launch_bounds__(256) void ln_lif_kernel(
    const float* __restrict__ gamma, const float* __restrict__ beta,
    float* __restrict__ outp, int final_out)
{
    __shared__ float srow[8][DDIM];
    int warp = threadIdx.x >> 5, lane = threadIdx.x & 31;
    int p = (blockIdx.x << 3) + warp;
    int b = p >> 8, l = p & 255;

    float g[24], bb[24], v[24], y[24];
    #pragma unroll
    for (int j = 0; j < 24; j++) {
        g[j]  = gamma[lane + (j << 5)];
        bb[j] = beta[lane + (j << 5)];
        v[j]  = 0.f;
    }

    for (int t = 0; t < 4; t++) {
        int r = t * NPOS + p;
        const float* row = g_Y + (size_t)r * DDIM;
        #pragma unroll
        for (int j = 0; j < 24; j++) {
            y[j] = row[lane + (j << 5)];
            srow[warp][lane + (j << 5)] = y[j];
        }
        __syncwarp();

        float mu = 0.f, rstd = 0.f;
        if (lane == 0) {
            float acc = 0.f;
            #pragma unroll 8
            for (int d = 0; d < DDIM; d++)
                acc = __fadd_rn(acc, srow[warp][d]);
            mu = __fdiv_rn(acc, 768.0f);
            float ssq = 0.f;
            #pragma unroll 8
            for (int d = 0; d < DDIM; d++) {
                float df = __fadd_rn(srow[warp][d], -mu);
                ssq = __fadd_rn(ssq, __fmul_rn(df, df));
            }
            float var = __fdiv_rn(ssq, 768.0f);
            rstd = __fdiv_rn(1.0f, __fsqrt_rn(__fadd_rn(var, 1e-5f)));
        }
        mu   = __shfl_sync(0xffffffffu, mu, 0);
        rstd = __shfl_sync(0xffffffffu, rstd, 0);

        if (final_out) {
            float* dst = outp + (size_t)((((b << 2) + t) << 8) + l) * DDIM;
            #pragma unroll
            for (int j = 0; j < 24; j++) {
                float h = __fadd_rn(
                    __fmul_rn(__fmul_rn(__fadd_rn(y[j], -mu), rstd), g[j]), bb[j]);
                float dlt = __fmul_rn(__fadd_rn(h, -v[j]), 0.5f);
                v[j] = __fadd_rn(v[j], dlt);
                float s = (v[j] >= 1.0f) ? 1.0f : 0.0f;
                dst[lane + (j << 5)] = s;
                v[j] = __fmul_rn(v[j], __fadd_rn(1.0f, -s));
            }
        } else {
            uint16_t* ip = g_idx + (size_t)r * DDIM;
            int base = 0, c1 = 0, c2 = 0;
            #pragma unroll
            for (int j = 0; j < 24; j++) {      // chunk j covers d=[32j,32j+32)
                float h = __fadd_rn(
                    __fmul_rn(__fmul_rn(__fadd_rn(y[j], -mu), rstd), g[j]), bb[j]);
                float dlt = __fmul_rn(__fadd_rn(h, -v[j]), 0.5f);
                v[j] = __fadd_rn(v[j], dlt);
                float s = (v[j] >= 1.0f) ? 1.0f : 0.0f;
                unsigned msk = __ballot_sync(0xffffffffu, s == 1.0f);
                if (s == 1.0f) {
                    int pos = base + __popc(msk & ((1u << lane) - 1u));
                    ip[pos] = (uint16_t)(lane + (j << 5));
                }
                base += __popc(msk);
                v[j] = __fmul_rn(v[j], __fadd_rn(1.0f, -s));
                if (j == 9)  c1 = base;   // d<320 boundary
                if (j == 19) c2 = base;   // d<640 boundary
            }
            if (lane == 0) g_cnt[r] = make_int4(c1, c2, base, 0);
        }
        __syncwarp();
    }
}

// ---------------------------------------------------------------------------
// Sparse layer-2 GEMM: spikes are 0/1; Eigen chain reduces to summing W2[e,d]
// over ascending nonzero d (bit-exact: fma(0,w,acc)==acc, fma(1,w,acc)==
// fadd(acc,w) in RN), keeping panel folds ((p0+p1)+p2)+bias.
// ---------------------------------------------------------------------------
__global__ __launch_bounds__(256) void spmm_kernel(const float* __restrict__ bias)
{
    int warp = threadIdx.x >> 5, lane = threadIdx.x & 31;
    int r = (blockIdx.x << 3) + warp;

    int4 cnt = g_cnt[r];
    int bounds[4] = {0, cnt.x, cnt.y, cnt.z};
    const uint16_t* idx = g_idx + (size_t)r * DDIM;

    float4 tot[6];
    #pragma unroll
    for (int j = 0; j < 6; j++) tot[j] = make_float4(0.f, 0.f, 0.f, 0.f);

    #pragma unroll
    for (int pnl = 0; pnl < 3; pnl++) {
        float4 pan[6];
        #pragma unroll
        for (int j = 0; j < 6; j++) pan[j] = make_float4(0.f, 0.f, 0.f, 0.f);
        int lo = bounds[pnl], hi = bounds[pnl + 1];
        for (int kb = lo; kb < hi; kb += 32) {
            int n = min(32, hi - kb);
            int myd = (kb + lane < hi) ? (int)idx[kb + lane] : 0;
            for (int kk = 0; kk < n; kk++) {
                int d = __shfl_sync(0xffffffffu, myd, kk);
                const float4* w = (const float4*)(g_Wt + d * DDIM);
                #pragma unroll
                for (int j = 0; j < 6; j++) {
                    float4 w4 = w[lane + (j << 5)];
                    pan[j].x = __fadd_rn(pan[j].x, w4.x);
                    pan[j].y = __fadd_rn(pan[j].y, w4.y);
                    pan[j].z = __fadd_rn(pan[j].z, w4.z);
                    pan[j].w = __fadd_rn(pan[j].w, w4.w);
                }
            }
        }
        #pragma unroll
        for (int j = 0; j < 6; j++) {
            tot[j].x = __fadd_rn(tot[j].x, pan[j].x);
            tot[j].y = __fadd_rn(tot[j].y, pan[j].y);
            tot[j].z = __fadd_rn(tot[j].z, pan[j].z);
            tot[j].w = __fadd_rn(tot[j].w, pan[j].w);
        }
    }

    float4* orow = (float4*)(g_Y + (size_t)r * DDIM);
    const float4* b4 = (const float4*)bias;
    #pragma unroll
    for (int j = 0; j < 6; j++) {
        int e4 = lane + (j << 5);
        float4 bbv = b4[e4];
        float4 o;
        o.x = __fadd_rn(tot[j].x, bbv.x);
        o.y = __fadd_rn(tot[j].y, bbv.y);
        o.z = __fadd_rn(tot[j].z, bbv.z);
        o.w = __fadd_rn(tot[j].w, bbv.w);
        orow[e4] = o;
    }
}

// ---------------------------------------------------------------------------
extern "C" void kernel_launch(void* const* d_in, const int* in_sizes, int n_in,
                              void* d_out, int out_size)
{
    const float* x   = (const float*)d_in[0];
    const float* W1  = (const float*)d_in[1];
    const float* b1  = (const float*)d_in[2];
    const float* g1  = (const float*)d_in[3];
    const float* be1 = (const float*)d_in[4];
    const float* W2  = (const float*)d_in[5];
    const float* b2  = (const float*)d_in[6];
    const float* g2  = (const float*)d_in[7];
    const float* be2 = (const float*)d_in[8];
    float* out = (float*)d_out;

    dim3 gg(DDIM / 128, MTOT / 128);   // (6, 256)

    transpose_kernel<<<dim3(24, 24), dim3(32, 8)>>>(W2);
    sgemm_kernel<<<gg, 256>>>(x, W1, b1);
    ln_lif_kernel<<<NPOS / 8, 256>>>(g1, be1, nullptr, 0);   // -> idx lists
    spmm_kernel<<<MTOT / 8, 256>>>(b2);                      // sparse GEMM2
    ln_lif_kernel<<<NPOS / 8, 256>>>(g2, be2, out, 1);       // -> final spikes
}